// round 16
// baseline (speedup 1.0000x reference)
#include <cuda_runtime.h>
#include <cuda_fp16.h>
#include <cstdint>

namespace {

constexpr int Bsz = 512, Msl = 32, DIN = 1024, DH = 4096, DOUT = 1024;
constexpr int BN = 128, BK = 128;
constexpr int TPB = 512;
constexpr int B_TILE = BK * BN * 2;       // 32 KB (fp16, [k][n] 256B rows)

// Intermediate h: [m][b][dh], fp16 (11-bit significand, same as tf32).
__device__ __half g_h[(size_t)Bsz * Msl * DH];
// x converted to fp16 and transposed to [m][b][k] (dense rows for layer-1 A).
__device__ __half g_x_h[(size_t)Msl * Bsz * DIN];

__device__ __forceinline__ uint32_t smem_u32(const void* p) {
    uint32_t a;
    asm("{ .reg .u64 t; cvta.to.shared.u64 t, %1; cvt.u32.u64 %0, t; }" : "=r"(a) : "l"(p));
    return a;
}
__device__ __forceinline__ void cp16(uint32_t dst, const void* src) {
    asm volatile("cp.async.cg.shared.global [%0], [%1], 16;" :: "r"(dst), "l"(src));
}
#define CP_COMMIT() asm volatile("cp.async.commit_group;" ::: "memory")
#define CP_WAIT0()  asm volatile("cp.async.wait_group 0;" ::: "memory")

__device__ __forceinline__ void ldsm4(uint32_t r[4], uint32_t addr) {
    asm volatile("ldmatrix.sync.aligned.m8n8.x4.shared.b16 {%0,%1,%2,%3}, [%4];"
                 : "=r"(r[0]), "=r"(r[1]), "=r"(r[2]), "=r"(r[3]) : "r"(addr));
}
__device__ __forceinline__ void ldsm4t(uint32_t r[4], uint32_t addr) {
    asm volatile("ldmatrix.sync.aligned.m8n8.x4.trans.shared.b16 {%0,%1,%2,%3}, [%4];"
                 : "=r"(r[0]), "=r"(r[1]), "=r"(r[2]), "=r"(r[3]) : "r"(addr));
}
__device__ __forceinline__ void mma_f16(float acc[4], const uint32_t a[4],
                                        uint32_t b0, uint32_t b1) {
    asm volatile(
        "mma.sync.aligned.m16n8k16.row.col.f32.f16.f16.f32 "
        "{%0,%1,%2,%3}, {%4,%5,%6,%7}, {%8,%9}, {%0,%1,%2,%3};\n"
        : "+f"(acc[0]), "+f"(acc[1]), "+f"(acc[2]), "+f"(acc[3])
        : "r"(a[0]), "r"(a[1]), "r"(a[2]), "r"(a[3]), "r"(b0), "r"(b1));
}
__device__ __forceinline__ uint32_t h2bits(__half2 h) {
    return *reinterpret_cast<uint32_t*>(&h);
}

// Pre-pass: x [b][m][k] fp32 -> x_h [m][b][k] fp16 (convert + transpose).
__global__ void __launch_bounds__(256)
cvt_f16_t(const float4* __restrict__ in, uint2* __restrict__ out, int n4) {
    int i = blockIdx.x * blockDim.x + threadIdx.x;
    if (i < n4) {
        float4 v = in[i];
        uint2 o;
        o.x = h2bits(__floats2half2_rn(v.x, v.y));
        o.y = h2bits(__floats2half2_rn(v.z, v.w));
        const int e   = i * 4;
        const int b   = e / (Msl * DIN);
        const int rem = e - b * (Msl * DIN);
        const int m   = rem / DIN;
        const int k   = rem - m * DIN;
        const size_t oo = ((size_t)m * Bsz + b) * DIN + k;
        out[oo / 4] = o;
    }
}

// C[BM_,128] tile of A[*,K](fp16) x W[K,*](fp32->fp16), +bias, opt ReLU.
// 512 threads, 16 warps as 4(m) x 4(n); warp tile (BM_/4) x 32. BK=128/stage,
// 2-stage smem ping-pong.
// BM_=256: layer 1 (2048 CTAs). BM_=128: layer 2 (1024 CTAs, kills the
// 3.46-wave tail; warp tile 32x32, acc halves -> more reg slack).
// A: cp.async fp16, smem [m][k] 256B rows, swizzle g^=(m&7).
// W: staged in TWO halves (64 k-rows) sharing one 16-reg set; conflict-free
//    STS (thread stores fp16 granules g and g+8 of its row). ldmatrix.x4.trans.
template<int BM_, bool RELU, bool OUT_HALF>
__global__ void __launch_bounds__(TPB, 1)
gemm_f16(const __half* __restrict__ Ag, const float* __restrict__ Wg,
         const float* __restrict__ biasg, void* __restrict__ Cg,
         int K,
         long aBatch, int lda, long wBatch, int ldw,
         long biasBatch, long cBatch, int ldc)
{
    constexpr int A_TILE_ = BM_ * BK * 2;
    constexpr int STAGE_  = A_TILE_ + B_TILE;
    constexpr int MT      = BM_ / 64;         // m16-subtiles per warp (4 or 2)
    constexpr int WROWS   = BM_ / 4;          // warp m-tile rows (64 or 32)

    extern __shared__ char sm[];
    const uint32_t sb = smem_u32(sm);

    const int tid  = threadIdx.x;
    const int lane = tid & 31, warp = tid >> 5;
    const int g = lane >> 2, tg = lane & 3;
    const int wm = warp & 3, wn = warp >> 2;          // 4 (m) x 4 (n)

    const int m0 = blockIdx.y * BM_;
    const int n0 = blockIdx.x * BN;
    const __half* A   = Ag    + (size_t)blockIdx.z * aBatch;
    const float* W    = Wg    + (size_t)blockIdx.z * wBatch;
    const float* bias = biasg + (size_t)blockIdx.z * biasBatch;

    // ---- A cp.async: BM_ rows x 256B; 512 threads x (BM_/32) ----
    const int a_kg = tid & 15;                // 16B granule in 256B row
    const int a_r  = tid >> 4;                // 0..31 (+32 each iter)
    const __half* a_src = A + (size_t)(m0 + a_r) * lda + a_kg * 8;
    const size_t a_rstep = (size_t)32 * lda;
    const uint32_t a_dst = sb + (uint32_t)(a_r * 256 + ((a_kg ^ (a_r & 7)) << 4));

    // ---- B: fp32 row r = tid>>3 (0..63 per half), g = tid&7 ----
    const int b_r = tid >> 3;
    const int b_g = tid & 7;
    const float* w0 = W + (size_t)b_r * ldw + n0 + b_g * 8;
    const size_t w_stage = (size_t)BK * ldw;          // 128 k-rows
    const size_t w_half  = (size_t)64 * ldw;
    const uint32_t b_q0 = (uint32_t)(b_r * 256 + (((b_g)     ^ (b_r & 7)) << 4));
    const uint32_t b_q1 = (uint32_t)(b_r * 256 + (((b_g + 8) ^ (b_r & 7)) << 4));
    constexpr uint32_t BHALF = 64 * 256;              // half1 smem offset

    // ---- ldmatrix per-thread pieces ----
    const int lrow = lane & 15;
    const int lhi  = lane >> 4;
    const int lr7  = lrow & 7;
    const uint32_t warpA = sb + (uint32_t)((wm * WROWS + lrow) * 256);
    const int nbase = wn * 4 + lhi;
    uint32_t boff[2];
    #pragma unroll
    for (int ng = 0; ng < 2; ++ng)
        boff[ng] = (uint32_t)(lrow * 256 + (((nbase + ng * 2) ^ lr7) << 4));

    float acc[MT][4][4];
    #pragma unroll
    for (int i = 0; i < MT; i++)
        #pragma unroll
        for (int j = 0; j < 4; j++)
            #pragma unroll
            for (int q = 0; q < 4; q++) acc[i][j][q] = 0.f;

    float4 rb0, rb1, rc0, rc1;                        // one shared 16-reg B set

    auto cpA = [&](int s, int buf) {
        const __half* src = a_src + (size_t)s * BK;
        const uint32_t d = a_dst + buf * STAGE_;
        #pragma unroll
        for (int it = 0; it < BM_ / 32; ++it)
            cp16(d + it * 8192, src + it * a_rstep);
    };
    auto ldgB = [&](const float* p) {
        rb0 = *(const float4*)(p);
        rb1 = *(const float4*)(p + 4);
        rc0 = *(const float4*)(p + 64);
        rc1 = *(const float4*)(p + 68);
    };
    auto stsB = [&](int buf, uint32_t halfoff) {
        uint4 v0, v1;
        v0.x = h2bits(__floats2half2_rn(rb0.x, rb0.y));
        v0.y = h2bits(__floats2half2_rn(rb0.z, rb0.w));
        v0.z = h2bits(__floats2half2_rn(rb1.x, rb1.y));
        v0.w = h2bits(__floats2half2_rn(rb1.z, rb1.w));
        v1.x = h2bits(__floats2half2_rn(rc0.x, rc0.y));
        v1.y = h2bits(__floats2half2_rn(rc0.z, rc0.w));
        v1.z = h2bits(__floats2half2_rn(rc1.x, rc1.y));
        v1.w = h2bits(__floats2half2_rn(rc1.z, rc1.w));
        char* bb = sm + buf * STAGE_ + A_TILE_ + halfoff;
        *(uint4*)(bb + b_q0) = v0;
        *(uint4*)(bb + b_q1) = v1;
    };

    auto compute4 = [&](int buf, int ksbase) {
        const uint32_t Ab = warpA + buf * STAGE_;
        const uint32_t Bb = sb + buf * STAGE_ + A_TILE_;
        #pragma unroll
        for (int ki = 0; ki < 4; ++ki) {
            const int ks = ksbase + ki;
            uint32_t af[MT][4];
            #pragma unroll
            for (int mt = 0; mt < MT; ++mt)
                ldsm4(af[mt], Ab + mt * 4096 +
                      (uint32_t)(((ks * 2 + lhi) ^ lr7) << 4));
            uint32_t bf[2][4];
            const uint32_t Bk = Bb + ks * 4096;
            ldsm4t(bf[0], Bk + boff[0]);
            ldsm4t(bf[1], Bk + boff[1]);
            #pragma unroll
            for (int mt = 0; mt < MT; ++mt)
                #pragma unroll
                for (int nt = 0; nt < 4; ++nt)
                    mma_f16(acc[mt][nt], af[mt],
                            bf[nt >> 1][(nt & 1) * 2], bf[nt >> 1][(nt & 1) * 2 + 1]);
        }
    };

    const int S = K / BK;                 // 8 (layer1) or 32 (layer2)

    // Preamble: A stage0 async; B stage0 both halves direct; h0 of stage1 in regs.
    cpA(0, 0); CP_COMMIT();
    ldgB(w0);                 stsB(0, 0);
    ldgB(w0 + w_half);        stsB(0, BHALF);
    ldgB(w0 + w_stage);       // stage-1 h0
    CP_WAIT0();
    __syncthreads();

    #pragma unroll 1
    for (int s = 0; s < S; ++s) {
        const int buf = s & 1, nbuf = buf ^ 1;

        if (s + 1 < S) {
            cpA(s + 1, nbuf); CP_COMMIT();
            stsB(nbuf, 0);                                  // h0(s+1), regs from prev iter
            ldgB(w0 + (size_t)(s + 1) * w_stage + w_half);  // h1(s+1)
        }
        compute4(buf, 0);
        if (s + 1 < S) {
            stsB(nbuf, BHALF);                              // h1(s+1)
            if (s + 2 < S)
                ldgB(w0 + (size_t)(s + 2) * w_stage);       // h0(s+2)
        }
        compute4(buf, 4);
        if (s + 1 < S) CP_WAIT0();
        __syncthreads();
    }

    // Epilogue: bias hoisted to nt-level, optional relu; fp16 or fp32 stores.
    {
        const int cb = n0 + wn * 32 + tg * 2;
        float bv[4][2];
        #pragma unroll
        for (int nt = 0; nt < 4; ++nt) {
            bv[nt][0] = bias[cb + nt * 8];
            bv[nt][1] = bias[cb + nt * 8 + 1];
        }
        #pragma unroll
        for (int mt = 0; mt < MT; ++mt) {
            const int r = m0 + wm * WROWS + mt * 16 + g;
            #pragma unroll
            for (int nt = 0; nt < 4; ++nt) {
                const int c = cb + nt * 8;
                float v0 = acc[mt][nt][0] + bv[nt][0];
                float v1 = acc[mt][nt][1] + bv[nt][1];
                float v2 = acc[mt][nt][2] + bv[nt][0];
                float v3 = acc[mt][nt][3] + bv[nt][1];
                if (RELU) {
                    v0 = fmaxf(v0, 0.f); v1 = fmaxf(v1, 0.f);
                    v2 = fmaxf(v2, 0.f); v3 = fmaxf(v3, 0.f);
                }
                if (OUT_HALF) {
                    __half* C = (__half*)Cg + (size_t)blockIdx.z * cBatch;
                    *(__half2*)(C + (size_t)r * ldc + c)       = __floats2half2_rn(v0, v1);
                    *(__half2*)(C + (size_t)(r + 8) * ldc + c) = __floats2half2_rn(v2, v3);
                } else {
                    float* C = (float*)Cg + (size_t)blockIdx.z * cBatch;
                    float2 p0; p0.x = v0; p0.y = v1;
                    float2 p1; p1.x = v2; p1.y = v3;
                    *(float2*)(C + (size_t)r * ldc + c)       = p0;
                    *(float2*)(C + (size_t)(r + 8) * ldc + c) = p1;
                }
            }
        }
    }
}

} // anonymous namespace

extern "C" void kernel_launch(void* const* d_in, const int* in_sizes, int n_in,
                              void* d_out, int out_size) {
    (void)in_sizes; (void)n_in; (void)out_size;
    const float* x  = (const float*)d_in[0];  // [B, M, DIN]
    const float* W1 = (const float*)d_in[1];  // [M, DIN, DH]
    const float* b1 = (const float*)d_in[2];  // [M, DH]
    const float* W2 = (const float*)d_in[3];  // [M, DH, DOUT]
    const float* b2 = (const float*)d_in[4];  // [M, DOUT]
    float* out = (float*)d_out;               // [B, M, DOUT]

    __half* h = nullptr;
    cudaGetSymbolAddress((void**)&h, g_h);
    __half* x_h = nullptr;
    cudaGetSymbolAddress((void**)&x_h, g_x_h);

    constexpr int SMEM1 = 2 * (256 * BK * 2 + B_TILE);   // 192 KB (BM=256)
    constexpr int SMEM2 = 2 * (128 * BK * 2 + B_TILE);   // 128 KB (BM=128)
    cudaFuncSetAttribute(gemm_f16<256, true, true>,
                         cudaFuncAttributeMaxDynamicSharedMemorySize, SMEM1);
    cudaFuncSetAttribute(gemm_f16<128, false, false>,
                         cudaFuncAttributeMaxDynamicSharedMemorySize, SMEM2);

    // Pre-pass: x -> fp16, transposed to [m][b][k]
    {
        const int n4 = Bsz * Msl * DIN / 4;
        cvt_f16_t<<<(n4 + 255) / 256, 256>>>((const float4*)x, (uint2*)x_h, n4);
    }

    dim3 blk(TPB);

    // Layer 1: BM=256, 2048 CTAs (13.8 waves, ~1% tail)
    dim3 g1(DH / BN, Bsz / 256, Msl);
    gemm_f16<256, true, true><<<g1, blk, SMEM1>>>(
        x_h, W1, b1, h, DIN,
        /*aBatch*/ (long)Bsz * DIN,  /*lda*/ DIN,
        /*wBatch*/ (long)DIN * DH,   /*ldw*/ DH,
        /*biasBatch*/ (long)DH,
        /*cBatch*/ (long)Bsz * DH,   /*ldc*/ DH);

    // Layer 2: BM=128, 1024 CTAs (6.92 waves, ~1% tail vs 3.46 waves before)
    dim3 g2(DOUT / BN, Bsz / 128, Msl);
    gemm_f16<128, false, false><<<g2, blk, SMEM2>>>(
        h, W2, b2, out, DH,
        /*aBatch*/ (long)Bsz * DH,   /*lda*/ DH,
        /*wBatch*/ (long)DH * DOUT,  /*ldw*/ DOUT,
        /*biasBatch*/ (long)DOUT,
        /*cBatch*/ (long)DOUT,       /*ldc*/ Msl * DOUT);
}

// round 17
// speedup vs baseline: 1.0924x; 1.0924x over previous
#include <cuda_runtime.h>
#include <cuda_fp16.h>
#include <cstdint>

namespace {

constexpr int Bsz = 512, Msl = 32, DIN = 1024, DH = 4096, DOUT = 1024;
constexpr int BM = 256, BN = 128, BK = 128;
constexpr int TPB = 512;
constexpr int A_TILE = BM * BK * 2;       // 64 KB (fp16, [m][k] 256B rows)
constexpr int B_TILE = BK * BN * 2;       // 32 KB (fp16, [k][n] 256B rows)
constexpr int STAGE  = A_TILE + B_TILE;   // 96 KB
constexpr int SMEM_DYN = 2 * STAGE;       // 192 KB ping-pong (1 CTA/SM)
constexpr int NSPLIT_FLAGS = 8 * 2 * 32;  // x-tiles * b-tiles * slots = 512

// Intermediate h: [m][b][dh], fp16 (11-bit significand, same as tf32).
__device__ __half g_h[(size_t)Bsz * Msl * DH];
// x converted to fp16 (pre-pass).
__device__ __half g_x_h[(size_t)Bsz * Msl * DIN];
// Layer-2 split-K partials: [m][b][n] fp32 (67 MB).
__device__ float g_p0[(size_t)Msl * Bsz * DOUT];
// Split-K handoff flags (re-zeroed every launch).
__device__ int g_flags[NSPLIT_FLAGS];

__device__ __forceinline__ uint32_t smem_u32(const void* p) {
    uint32_t a;
    asm("{ .reg .u64 t; cvta.to.shared.u64 t, %1; cvt.u32.u64 %0, t; }" : "=r"(a) : "l"(p));
    return a;
}
__device__ __forceinline__ void cp16(uint32_t dst, const void* src) {
    asm volatile("cp.async.cg.shared.global [%0], [%1], 16;" :: "r"(dst), "l"(src));
}
#define CP_COMMIT() asm volatile("cp.async.commit_group;" ::: "memory")
#define CP_WAIT0()  asm volatile("cp.async.wait_group 0;" ::: "memory")

__device__ __forceinline__ void ldsm4(uint32_t r[4], uint32_t addr) {
    asm volatile("ldmatrix.sync.aligned.m8n8.x4.shared.b16 {%0,%1,%2,%3}, [%4];"
                 : "=r"(r[0]), "=r"(r[1]), "=r"(r[2]), "=r"(r[3]) : "r"(addr));
}
__device__ __forceinline__ void ldsm4t(uint32_t r[4], uint32_t addr) {
    asm volatile("ldmatrix.sync.aligned.m8n8.x4.trans.shared.b16 {%0,%1,%2,%3}, [%4];"
                 : "=r"(r[0]), "=r"(r[1]), "=r"(r[2]), "=r"(r[3]) : "r"(addr));
}
__device__ __forceinline__ void mma_f16(float acc[4], const uint32_t a[4],
                                        uint32_t b0, uint32_t b1) {
    asm volatile(
        "mma.sync.aligned.m16n8k16.row.col.f32.f16.f16.f32 "
        "{%0,%1,%2,%3}, {%4,%5,%6,%7}, {%8,%9}, {%0,%1,%2,%3};\n"
        : "+f"(acc[0]), "+f"(acc[1]), "+f"(acc[2]), "+f"(acc[3])
        : "r"(a[0]), "r"(a[1]), "r"(a[2]), "r"(a[3]), "r"(b0), "r"(b1));
}
__device__ __forceinline__ uint32_t h2bits(__half2 h) {
    return *reinterpret_cast<uint32_t*>(&h);
}

// Pre-pass: x fp32 -> fp16 (round-14 proven version).
__global__ void __launch_bounds__(256)
cvt_f16(const float4* __restrict__ in, uint2* __restrict__ out, int n4) {
    int i = blockIdx.x * blockDim.x + threadIdx.x;
    if (i < n4) {
        float4 v = in[i];
        uint2 o;
        o.x = h2bits(__floats2half2_rn(v.x, v.y));
        o.y = h2bits(__floats2half2_rn(v.z, v.w));
        out[i] = o;
    }
}

__global__ void zero_flags(int* f) { f[threadIdx.x] = 0; }

// C[BM=256,BN=128] tile of A[*,K](fp16) x W[K,*](fp32->fp16). Round-14 body.
// MODE 0: layer 1 — +bias, ReLU, fp16 store (h).
// MODE 1: layer 2 split-K=2 — blockIdx.z = m + 32*split, K=2048 per split.
//   split 0: p0 = acc + bias (fp32, [m][b][n]); release per-tile flag.
//   split 1: acquire flag (partner is 512 bids earlier: >=2.4 waves margin,
//            never actually spins; bid order precludes deadlock), then
//            out = acc + ldcg(p0) (fp32).
template<int MODE>
__global__ void __launch_bounds__(TPB, 1)
gemm_f16(const __half* __restrict__ Ag, const float* __restrict__ Wg,
         const float* __restrict__ biasg, void* __restrict__ Cg,
         int K,
         long aBatch, int lda, long wBatch, int ldw,
         long biasBatch, long cBatch, int ldc,
         float* __restrict__ p0buf, int* __restrict__ flags)
{
    extern __shared__ char sm[];
    const uint32_t sb = smem_u32(sm);

    const int tid  = threadIdx.x;
    const int lane = tid & 31, warp = tid >> 5;
    const int g = lane >> 2, tg = lane & 3;
    const int wm = warp & 3, wn = warp >> 2;          // 4 (m) x 4 (n)

    const int mslot = (MODE == 0) ? blockIdx.z : (blockIdx.z & 31);
    const int split = (MODE == 0) ? 0 : (blockIdx.z >> 5);
    const int kOff  = split * K;

    const int m0 = blockIdx.y * BM;
    const int n0 = blockIdx.x * BN;
    const __half* A   = Ag    + (size_t)mslot * aBatch;
    const float* W    = Wg    + (size_t)mslot * wBatch;
    const float* bias = biasg + (size_t)mslot * biasBatch;

    // ---- A cp.async: 256 rows x 256B = 4096 cp16; 512 threads x 8 ----
    const int a_kg = tid & 15;                // 16B granule in 256B row
    const int a_r  = tid >> 4;                // 0..31 (+32 x7)
    const __half* a_src = A + (size_t)(m0 + a_r) * lda + kOff + a_kg * 8;
    const size_t a_rstep = (size_t)32 * lda;
    const uint32_t a_dst = sb + (uint32_t)(a_r * 256 + ((a_kg ^ (a_r & 7)) << 4));

    // ---- B: fp32 row r = tid>>3 (0..63 per half), g = tid&7 ----
    const int b_r = tid >> 3;
    const int b_g = tid & 7;
    const float* w0 = W + (size_t)(b_r + kOff) * ldw + n0 + b_g * 8;
    const size_t w_stage = (size_t)BK * ldw;          // 128 k-rows
    const size_t w_half  = (size_t)64 * ldw;
    const uint32_t b_q0 = (uint32_t)(b_r * 256 + (((b_g)     ^ (b_r & 7)) << 4));
    const uint32_t b_q1 = (uint32_t)(b_r * 256 + (((b_g + 8) ^ (b_r & 7)) << 4));
    constexpr uint32_t BHALF = 64 * 256;              // half1 smem offset

    // ---- ldmatrix per-thread pieces ----
    const int lrow = lane & 15;
    const int lhi  = lane >> 4;
    const int lr7  = lrow & 7;
    const uint32_t warpA = sb + (uint32_t)((wm * 64 + lrow) * 256);
    const int nbase = wn * 4 + lhi;
    uint32_t boff[2];
    #pragma unroll
    for (int ng = 0; ng < 2; ++ng)
        boff[ng] = (uint32_t)(lrow * 256 + (((nbase + ng * 2) ^ lr7) << 4));

    float acc[4][4][4];
    #pragma unroll
    for (int i = 0; i < 4; i++)
        #pragma unroll
        for (int j = 0; j < 4; j++)
            #pragma unroll
            for (int q = 0; q < 4; q++) acc[i][j][q] = 0.f;

    float4 rb0, rb1, rc0, rc1;                        // one shared 16-reg B set

    auto cpA = [&](int s, int buf) {
        const __half* src = a_src + (size_t)s * BK;
        const uint32_t d = a_dst + buf * STAGE;
        #pragma unroll
        for (int it = 0; it < 8; ++it)
            cp16(d + it * 8192, src + it * a_rstep);
    };
    auto ldgB = [&](const float* p) {
        rb0 = *(const float4*)(p);
        rb1 = *(const float4*)(p + 4);
        rc0 = *(const float4*)(p + 64);
        rc1 = *(const float4*)(p + 68);
    };
    auto stsB = [&](int buf, uint32_t halfoff) {
        uint4 v0, v1;
        v0.x = h2bits(__floats2half2_rn(rb0.x, rb0.y));
        v0.y = h2bits(__floats2half2_rn(rb0.z, rb0.w));
        v0.z = h2bits(__floats2half2_rn(rb1.x, rb1.y));
        v0.w = h2bits(__floats2half2_rn(rb1.z, rb1.w));
        v1.x = h2bits(__floats2half2_rn(rc0.x, rc0.y));
        v1.y = h2bits(__floats2half2_rn(rc0.z, rc0.w));
        v1.z = h2bits(__floats2half2_rn(rc1.x, rc1.y));
        v1.w = h2bits(__floats2half2_rn(rc1.z, rc1.w));
        char* bb = sm + buf * STAGE + A_TILE + halfoff;
        *(uint4*)(bb + b_q0) = v0;
        *(uint4*)(bb + b_q1) = v1;
    };

    auto compute4 = [&](int buf, int ksbase) {
        const uint32_t Ab = warpA + buf * STAGE;
        const uint32_t Bb = sb + buf * STAGE + A_TILE;
        #pragma unroll
        for (int ki = 0; ki < 4; ++ki) {
            const int ks = ksbase + ki;
            uint32_t af[4][4];
            #pragma unroll
            for (int mt = 0; mt < 4; ++mt)
                ldsm4(af[mt], Ab + mt * 4096 +
                      (uint32_t)(((ks * 2 + lhi) ^ lr7) << 4));
            uint32_t bf[2][4];
            const uint32_t Bk = Bb + ks * 4096;
            ldsm4t(bf[0], Bk + boff[0]);
            ldsm4t(bf[1], Bk + boff[1]);
            #pragma unroll
            for (int mt = 0; mt < 4; ++mt)
                #pragma unroll
                for (int nt = 0; nt < 4; ++nt)
                    mma_f16(acc[mt][nt], af[mt],
                            bf[nt >> 1][(nt & 1) * 2], bf[nt >> 1][(nt & 1) * 2 + 1]);
        }
    };

    const int S = K / BK;                 // 8 (layer1) or 16 (layer2 split)

    // Preamble: A stage0 async; B stage0 both halves direct; h0 of stage1 in regs.
    cpA(0, 0); CP_COMMIT();
    ldgB(w0);                 stsB(0, 0);
    ldgB(w0 + w_half);        stsB(0, BHALF);
    ldgB(w0 + w_stage);       // stage-1 h0
    CP_WAIT0();
    __syncthreads();

    #pragma unroll 1
    for (int s = 0; s < S; ++s) {
        const int buf = s & 1, nbuf = buf ^ 1;

        if (s + 1 < S) {
            cpA(s + 1, nbuf); CP_COMMIT();
            stsB(nbuf, 0);                                  // h0(s+1), regs from prev iter
            ldgB(w0 + (size_t)(s + 1) * w_stage + w_half);  // h1(s+1)
        }
        compute4(buf, 0);
        if (s + 1 < S) {
            stsB(nbuf, BHALF);                              // h1(s+1)
            if (s + 2 < S)
                ldgB(w0 + (size_t)(s + 2) * w_stage);       // h0(s+2)
        }
        compute4(buf, 4);
        if (s + 1 < S) CP_WAIT0();
        __syncthreads();
    }

    // ================= Epilogues =================
    if (MODE == 0) {
        // layer 1: +bias, relu, fp16 store (round-14 exact path)
        #pragma unroll
        for (int mt = 0; mt < 4; ++mt) {
            const int r = m0 + wm * 64 + mt * 16 + g;
            #pragma unroll
            for (int nt = 0; nt < 4; ++nt) {
                const int c = n0 + wn * 32 + nt * 8 + tg * 2;
                const float b0v = bias[c], b1v = bias[c + 1];
                float v0 = fmaxf(acc[mt][nt][0] + b0v, 0.f);
                float v1 = fmaxf(acc[mt][nt][1] + b1v, 0.f);
                float v2 = fmaxf(acc[mt][nt][2] + b0v, 0.f);
                float v3 = fmaxf(acc[mt][nt][3] + b1v, 0.f);
                __half* C = (__half*)Cg + (size_t)mslot * cBatch;
                *(__half2*)(C + (size_t)r * ldc + c)       = __floats2half2_rn(v0, v1);
                *(__half2*)(C + (size_t)(r + 8) * ldc + c) = __floats2half2_rn(v2, v3);
            }
        }
    } else {
        const int tile = blockIdx.x + 8 * blockIdx.y + 16 * mslot;  // < 512
        float* P = p0buf + (size_t)mslot * Bsz * DOUT;
        if (split == 0) {
            // p0 = acc + bias (no relu), then release flag
            #pragma unroll
            for (int mt = 0; mt < 4; ++mt) {
                const int r = m0 + wm * 64 + mt * 16 + g;
                #pragma unroll
                for (int nt = 0; nt < 4; ++nt) {
                    const int c = n0 + wn * 32 + nt * 8 + tg * 2;
                    const float b0v = bias[c], b1v = bias[c + 1];
                    float2 p0v; p0v.x = acc[mt][nt][0] + b0v; p0v.y = acc[mt][nt][1] + b1v;
                    float2 p1v; p1v.x = acc[mt][nt][2] + b0v; p1v.y = acc[mt][nt][3] + b1v;
                    *(float2*)(P + (size_t)r * DOUT + c)       = p0v;
                    *(float2*)(P + (size_t)(r + 8) * DOUT + c) = p1v;
                }
            }
            __threadfence();
            __syncthreads();
            if (tid == 0)
                asm volatile("st.release.gpu.global.b32 [%0], %1;"
                             :: "l"(flags + tile), "r"(1) : "memory");
        } else {
            // acquire partner's partial, out = acc + p0
            if (tid == 0) {
                int v;
                do {
                    asm volatile("ld.acquire.gpu.global.b32 %0, [%1];"
                                 : "=r"(v) : "l"(flags + tile) : "memory");
                } while (v == 0);
            }
            __syncthreads();
            float* C = (float*)Cg + (size_t)mslot * cBatch;
            #pragma unroll
            for (int mt = 0; mt < 4; ++mt) {
                const int r = m0 + wm * 64 + mt * 16 + g;
                #pragma unroll
                for (int nt = 0; nt < 4; ++nt) {
                    const int c = n0 + wn * 32 + nt * 8 + tg * 2;
                    const float2 q0 = __ldcg((const float2*)(P + (size_t)r * DOUT + c));
                    const float2 q1 = __ldcg((const float2*)(P + (size_t)(r + 8) * DOUT + c));
                    float2 o0; o0.x = acc[mt][nt][0] + q0.x; o0.y = acc[mt][nt][1] + q0.y;
                    float2 o1; o1.x = acc[mt][nt][2] + q1.x; o1.y = acc[mt][nt][3] + q1.y;
                    *(float2*)(C + (size_t)r * ldc + c)       = o0;
                    *(float2*)(C + (size_t)(r + 8) * ldc + c) = o1;
                }
            }
        }
    }
}

} // anonymous namespace

extern "C" void kernel_launch(void* const* d_in, const int* in_sizes, int n_in,
                              void* d_out, int out_size) {
    (void)in_sizes; (void)n_in; (void)out_size;
    const float* x  = (const float*)d_in[0];  // [B, M, DIN]
    const float* W1 = (const float*)d_in[1];  // [M, DIN, DH]
    const float* b1 = (const float*)d_in[2];  // [M, DH]
    const float* W2 = (const float*)d_in[3];  // [M, DH, DOUT]
    const float* b2 = (const float*)d_in[4];  // [M, DOUT]
    float* out = (float*)d_out;               // [B, M, DOUT]

    __half* h = nullptr;   cudaGetSymbolAddress((void**)&h, g_h);
    __half* x_h = nullptr; cudaGetSymbolAddress((void**)&x_h, g_x_h);
    float* p0 = nullptr;   cudaGetSymbolAddress((void**)&p0, g_p0);
    int* flags = nullptr;  cudaGetSymbolAddress((void**)&flags, g_flags);

    cudaFuncSetAttribute(gemm_f16<0>, cudaFuncAttributeMaxDynamicSharedMemorySize, SMEM_DYN);
    cudaFuncSetAttribute(gemm_f16<1>, cudaFuncAttributeMaxDynamicSharedMemorySize, SMEM_DYN);

    // Pre-pass: x -> fp16; zero split-K flags
    {
        const int n4 = Bsz * Msl * DIN / 4;
        cvt_f16<<<(n4 + 255) / 256, 256>>>((const float4*)x, (uint2*)x_h, n4);
        zero_flags<<<1, NSPLIT_FLAGS>>>(flags);
    }

    dim3 blk(TPB);

    // Layer 1: per m, h[b, n] = fp16(relu(x[b,:] @ W1 + b1)) — round-14 config
    dim3 g1(DH / BN, Bsz / BM, Msl);
    gemm_f16<0><<<g1, blk, SMEM_DYN>>>(
        x_h, W1, b1, h, DIN,
        /*aBatch*/ (long)DIN,        /*lda*/ Msl * DIN,
        /*wBatch*/ (long)DIN * DH,   /*ldw*/ DH,
        /*biasBatch*/ (long)DH,
        /*cBatch*/ (long)Bsz * DH,   /*ldc*/ DH,
        nullptr, nullptr);

    // Layer 2: split-K=2, one launch of 1024 CTAs (grid.z = m + 32*split),
    // each K=2048; split-0 -> p0(+bias), split-1 -> out = acc + p0.
    dim3 g2(DOUT / BN, Bsz / BM, Msl * 2);
    gemm_f16<1><<<g2, blk, SMEM_DYN>>>(
        h, W2, b2, out, DH / 2,
        /*aBatch*/ (long)Bsz * DH,   /*lda*/ DH,
        /*wBatch*/ (long)DH * DOUT,  /*ldw*/ DOUT,
        /*biasBatch*/ (long)DOUT,
        /*cBatch*/ (long)DOUT,       /*ldc*/ Msl * DOUT,
        p0, flags);
}